// round 14
// baseline (speedup 1.0000x reference)
#include <cuda_runtime.h>
#include <math.h>

// Problem constants
#define B_   4
#define H_   16
#define NF_  32
#define P_   16
#define M_   257          // P*P + 1
#define S_   (NF_ * M_)   // 8224
#define D_   64
#define NTOK (B_ * H_ * S_)   // 526336 tokens per tensor

// ---------------------------------------------------------------------------
// Pure-fp32 sincos for |x| <= ~403 rad.
// Cody-Waite: 2*pi = C0 + C1 with C0 = 6.28125 (9 mantissa bits, so k*C0 is
// EXACT for k <= 64) and C1 = 2*pi - 6.28125 = 1.9353071795864769e-3.
// Then MUFU __sinf/__cosf on [-pi, pi]: abs err ~4e-7. Gate is 1e-3.
// ---------------------------------------------------------------------------
__device__ __forceinline__ float2 fast_cs(float f) {
    const float INV_2PI = 0.15915494309189533f;
    const float C0 = 6.28125f;                    // exact; k*C0 exact (k<=64)
    const float C1 = 1.9353071795864769e-3f;      // 2*pi - C0, correctly rounded
    float kf = rintf(f * INV_2PI);
    float r  = fmaf(-kf, C0, f);
    r        = fmaf(-kf, C1, r);
    return make_float2(__cosf(r), __sinf(r));
}

// Freq element index for pair p at grid cell (frame, r, c).
// freqs shape (32,17,17,30): dims [0,10) depend on frame, [10,20) on r,
// [20,30) on c; adjacent dims repeat -> pair p uses element 2*(p%5) of its
// axis block. Working set: ~330 distinct addresses -> L1/L2-resident.
__device__ __forceinline__ int freq_idx(int p, int frame, int r, int c) {
    if (p < 5)  return frame * (17 * 17 * 30) + 2 * p;
    if (p < 10) return r * (17 * 30) + 10 + 2 * (p - 5);
    return c * 30 + 20 + 2 * (p - 10);
}

// ---------------------------------------------------------------------------
// Single fused kernel, no smem/table/barrier. 8 threads per seq-position;
// thread t handles float4 chunks t (rotated) and t+8 (copy) of BOTH the q
// and k tokens at the same (b,h,s). 4 independent streaming loads (.cs);
// stores use default policy (lets LTS assemble full lines). Two cos/sin
// pairs computed inline, amortized across q and k; lane-7 identity is
// branchless (clamped index + predicated select).
// ---------------------------------------------------------------------------
__global__ __launch_bounds__(256) void frame_rope_kernel(
        const float*  __restrict__ freqs,
        const float4* __restrict__ q,
        const float4* __restrict__ k,
        float4*       __restrict__ out) {
    unsigned gid = blockIdx.x * blockDim.x + threadIdx.x;   // < NTOK*8
    unsigned t   = gid & 7u;        // chunk id within token (0..7)
    unsigned tok = gid >> 3;        // token id (same for q and k)

    const float4* qb = q + tok * 16;
    const float4* kb = k + tok * 16;
    // Front-batch all four independent streaming loads (single-use data).
    float4 q0 = __ldcs(qb + t);
    float4 q1 = __ldcs(qb + t + 8);
    float4 k0 = __ldcs(kb + t);
    float4 k1 = __ldcs(kb + t + 8);

    // Position -> (frame, r, c); audio token (m==256) -> cell (16,16).
    unsigned s     = tok % S_;
    unsigned frame = s / M_;
    unsigned m     = s - frame * M_;
    unsigned r, c;
    if (m == 256u) { r = 16u; c = 16u; }
    else           { r = m >> 4; c = m & 15u; }

    // Inline cos/sin for pairs p0 = 2t and p0+1 (pair 15 -> identity).
    int p0 = 2 * (int)t;
    int p1 = p0 + 1;
    float f0 = __ldg(freqs + freq_idx(p0, frame, r, c));
    float f1 = __ldg(freqs + freq_idx(p1 < 15 ? p1 : 14, frame, r, c));
    float2 cs0 = fast_cs(f0);
    float2 cs1 = fast_cs(f1);
    if (p1 == 15) { cs1.x = 1.0f; cs1.y = 0.0f; }   // predicated select

    float4 oq, ok;
    oq.x = q0.x * cs0.x - q0.y * cs0.y;
    oq.y = q0.y * cs0.x + q0.x * cs0.y;
    oq.z = q0.z * cs1.x - q0.w * cs1.y;
    oq.w = q0.w * cs1.x + q0.z * cs1.y;
    ok.x = k0.x * cs0.x - k0.y * cs0.y;
    ok.y = k0.y * cs0.x + k0.x * cs0.y;
    ok.z = k0.z * cs1.x - k0.w * cs1.y;
    ok.w = k0.w * cs1.x + k0.z * cs1.y;

    // Default-policy stores: allow full-line coalescing in LTS.
    float4* oqb = out + tok * 16;
    float4* okb = out + (NTOK + tok) * 16;
    oqb[t]     = oq;
    oqb[t + 8] = q1;
    okb[t]     = ok;
    okb[t + 8] = k1;
}

extern "C" void kernel_launch(void* const* d_in, const int* in_sizes, int n_in,
                              void* d_out, int out_size) {
    const float* q     = (const float*)d_in[0];
    const float* k     = (const float*)d_in[1];
    const float* freqs = (const float*)d_in[2];

    const int total_threads = NTOK * 8;   // 4,210,688 -> 16,448 blocks
    frame_rope_kernel<<<total_threads / 256, 256>>>(
        freqs, (const float4*)q, (const float4*)k, (float4*)d_out);
}

// round 15
// speedup vs baseline: 1.0194x; 1.0194x over previous
#include <cuda_runtime.h>
#include <math.h>

// Problem constants
#define B_   4
#define H_   16
#define NF_  32
#define P_   16
#define M_   257          // P*P + 1
#define S_   (NF_ * M_)   // 8224
#define D_   64
#define NTOK (B_ * H_ * S_)   // 526336 tokens per tensor

// ---------------------------------------------------------------------------
// Pure-fp32 sincos for |x| <= ~403 rad.
// Cody-Waite: 2*pi = C0 + C1 with C0 = 6.28125 (9 mantissa bits, so k*C0 is
// EXACT for k <= 64) and C1 = 2*pi - 6.28125 = 1.9353071795864769e-3
// (correctly rounded; omitted residual contributes < 1e-8 rad).
// Then MUFU __sinf/__cosf on [-pi, pi]: abs err ~4e-7. Gate is 1e-3.
// ---------------------------------------------------------------------------
__device__ __forceinline__ float2 fast_cs(float f) {
    const float INV_2PI = 0.15915494309189533f;
    const float C0 = 6.28125f;                    // exact; k*C0 exact (k<=64)
    const float C1 = 1.9353071795864769e-3f;      // 2*pi - C0, correctly rounded
    float kf = rintf(f * INV_2PI);
    float r  = fmaf(-kf, C0, f);
    r        = fmaf(-kf, C1, r);
    return make_float2(__cosf(r), __sinf(r));
}

// Freq element index for pair p at grid cell (frame, r, c).
// freqs shape (32,17,17,30): dims [0,10) depend on frame, [10,20) on r,
// [20,30) on c; adjacent dims repeat, so pair p uses element 2*(p%5) of its
// axis block. Working set: ~330 distinct addresses -> L1-resident.
__device__ __forceinline__ int freq_idx(int p, int frame, int r, int c) {
    if (p < 5)  return frame * (17 * 17 * 30) + 2 * p;
    if (p < 10) return r * (17 * 30) + 10 + 2 * (p - 5);
    return c * 30 + 20 + 2 * (p - 10);
}

// ---------------------------------------------------------------------------
// Single fused kernel, no smem/barrier/table. 8 threads per seq-position;
// thread t handles float4 chunks t (rotated) and t+8 (copy) of BOTH the q
// and k tokens at the same (b,h,s). 4 independent streaming loads; streaming
// (.cs) stores keep the single-use write stream from polluting L2 (measured:
// default-policy stores cost ~1.6us). Two cos/sin pairs computed inline
// (fp32 Cody-Waite + MUFU), amortized across q and k.
// ---------------------------------------------------------------------------
__global__ __launch_bounds__(256) void frame_rope_kernel(
        const float*  __restrict__ freqs,
        const float4* __restrict__ q,
        const float4* __restrict__ k,
        float4*       __restrict__ out) {
    int gid = blockIdx.x * blockDim.x + threadIdx.x;   // < NTOK*8
    int t   = gid & 7;          // chunk id within token (0..7)
    int tok = gid >> 3;         // token id (same for q and k)

    const float4* qb = q + tok * 16;
    const float4* kb = k + tok * 16;
    // Front-batch all four independent streaming loads (single-use data).
    float4 q0 = __ldcs(qb + t);
    float4 q1 = __ldcs(qb + t + 8);
    float4 k0 = __ldcs(kb + t);
    float4 k1 = __ldcs(kb + t + 8);

    // Position -> (frame, r, c); audio token (m==256) -> cell (16,16).
    int s     = tok % S_;
    int frame = s / M_;
    int m     = s - frame * M_;
    int r, c;
    if (m == 256) { r = 16; c = 16; }
    else          { r = m >> 4; c = m & 15; }

    // Inline cos/sin for pairs p0 = 2t and p0+1 (p0+1==15 -> identity).
    int p0 = 2 * t;
    float f0 = __ldg(freqs + freq_idx(p0, frame, r, c));
    float2 cs0 = fast_cs(f0);
    float2 cs1 = make_float2(1.0f, 0.0f);
    if (t < 7) {
        float f1 = __ldg(freqs + freq_idx(p0 + 1, frame, r, c));
        cs1 = fast_cs(f1);
    }

    float4 oq, ok;
    oq.x = q0.x * cs0.x - q0.y * cs0.y;
    oq.y = q0.y * cs0.x + q0.x * cs0.y;
    oq.z = q0.z * cs1.x - q0.w * cs1.y;
    oq.w = q0.w * cs1.x + q0.z * cs1.y;
    ok.x = k0.x * cs0.x - k0.y * cs0.y;
    ok.y = k0.y * cs0.x + k0.x * cs0.y;
    ok.z = k0.z * cs1.x - k0.w * cs1.y;
    ok.w = k0.w * cs1.x + k0.z * cs1.y;

    float4* oqb = out + tok * 16;
    float4* okb = out + (NTOK + tok) * 16;
    __stcs(oqb + t,     oq);
    __stcs(oqb + t + 8, q1);
    __stcs(okb + t,     ok);
    __stcs(okb + t + 8, k1);
}

extern "C" void kernel_launch(void* const* d_in, const int* in_sizes, int n_in,
                              void* d_out, int out_size) {
    const float* q     = (const float*)d_in[0];
    const float* k     = (const float*)d_in[1];
    const float* freqs = (const float*)d_in[2];

    const int total_threads = NTOK * 8;   // 4,210,688 -> 16,448 blocks
    frame_rope_kernel<<<total_threads / 256, 256>>>(
        freqs, (const float4*)q, (const float4*)k, (float4*)d_out);
}